// round 2
// baseline (speedup 1.0000x reference)
#include <cuda_runtime.h>

#define B_  4
#define S_  2048
#define DM_ 512
#define H_  8
#define DK_ 64
#define SCALE_ 0.125f

// ---------------- scratch (device globals: allocation-free rule) -------------
__device__ float g_Q[B_*H_*S_*DK_];            // [B,H,S,DK]
__device__ float g_K[B_*H_*S_*DK_];
__device__ float g_V[B_*H_*S_*DK_];
__device__ float g_P[H_*S_*DK_];               // [H,S,DK]
__device__ float g_A[(size_t)B_*H_*S_*S_];     // pos matrix before shift [BH,S,S]
__device__ float g_ctx[B_*S_*DM_];             // attention output, [B,S,DM]

// ---------------------------------------------------------------------------
// Generic C = X[M,512] @ W[512,512].
// SPLIT=1: head-split layout out[((b*H+h)*S+s)*DK+d]; SPLIT=0: row-major.
// ---------------------------------------------------------------------------
template<int SPLIT>
__global__ __launch_bounds__(256) void gemm512_kernel(
    const float* __restrict__ X, const float* __restrict__ W,
    float* __restrict__ out)
{
    __shared__ float As[64*17];
    __shared__ float Bs[16*64];
    const int tid = threadIdx.x;
    const int ty4 = (tid >> 4) * 4;
    const int tx  = tid & 15;
    const int m0 = blockIdx.x * 64;
    const int n0 = blockIdx.y * 64;

    float acc[4][4];
#pragma unroll
    for (int i = 0; i < 4; i++)
#pragma unroll
        for (int j = 0; j < 4; j++) acc[i][j] = 0.f;

    for (int k0 = 0; k0 < 512; k0 += 16) {
        {   // A tile 64x16
            int r = tid >> 2, c = (tid & 3) * 4;
            float4 a4 = *(const float4*)&X[(size_t)(m0 + r)*512 + k0 + c];
            As[r*17 + c + 0] = a4.x; As[r*17 + c + 1] = a4.y;
            As[r*17 + c + 2] = a4.z; As[r*17 + c + 3] = a4.w;
        }
        {   // B tile 16x64
            int r = tid >> 4, c = (tid & 15) * 4;
            *(float4*)&Bs[r*64 + c] =
                *(const float4*)&W[(size_t)(k0 + r)*512 + n0 + c];
        }
        __syncthreads();
#pragma unroll
        for (int kk = 0; kk < 16; kk++) {
            float av[4];
#pragma unroll
            for (int i = 0; i < 4; i++) av[i] = As[(ty4 + i)*17 + kk];
            const float4 b4 = *(const float4*)&Bs[kk*64 + tx*4];
            const float bv[4] = {b4.x, b4.y, b4.z, b4.w};
#pragma unroll
            for (int i = 0; i < 4; i++)
#pragma unroll
                for (int j = 0; j < 4; j++)
                    acc[i][j] = fmaf(av[i], bv[j], acc[i][j]);
        }
        __syncthreads();
    }

#pragma unroll
    for (int i = 0; i < 4; i++) {
        const int mm = m0 + ty4 + i;
        const int nn = n0 + tx*4;
        float4 o4 = make_float4(acc[i][0], acc[i][1], acc[i][2], acc[i][3]);
        if (SPLIT) {
            int bb = mm >> 11, ss = mm & 2047;
            int hh = nn >> 6,  dd = nn & 63;
            *(float4*)&out[((size_t)(bb*H_ + hh)*S_ + ss)*DK_ + dd] = o4;
        } else {
            *(float4*)&out[(size_t)mm*512 + nn] = o4;
        }
    }
}

// ---------------------------------------------------------------------------
// A[bh,i,k] = sum_d (Q[bh,i,d] + v_bias[h,d]) * P[h,k,d].  64x64 tile, K=64.
// ---------------------------------------------------------------------------
__global__ __launch_bounds__(256) void posA_kernel(
    const float* __restrict__ Qg0, const float* __restrict__ Pg0,
    const float* __restrict__ v_bias, float* __restrict__ Ag0)
{
    __shared__ float Qs[64*65];
    __shared__ float Ps[64*65];
    const int tid = threadIdx.x;
    const int ty4 = (tid >> 4) * 4;
    const int tx  = tid & 15;
    const int k0 = blockIdx.x * 64;
    const int i0 = blockIdx.y * 64;
    const int bh = blockIdx.z;
    const int h  = bh & 7;
    const float* Qg = Qg0 + (size_t)bh * S_ * DK_;
    const float* Pg = Pg0 + (size_t)h  * S_ * DK_;

    const int lr = tid >> 4;
    const int lc = (tid & 15) * 4;
#pragma unroll
    for (int rr = 0; rr < 4; rr++) {
        int r = lr + rr*16;
        float4 qv = *(const float4*)&Qg[(size_t)(i0 + r)*DK_ + lc];
        const float4 vb = *(const float4*)&v_bias[h*DK_ + lc];
        qv.x += vb.x; qv.y += vb.y; qv.z += vb.z; qv.w += vb.w;
        Qs[r*65 + lc + 0] = qv.x; Qs[r*65 + lc + 1] = qv.y;
        Qs[r*65 + lc + 2] = qv.z; Qs[r*65 + lc + 3] = qv.w;
        float4 pv = *(const float4*)&Pg[(size_t)(k0 + r)*DK_ + lc];
        Ps[r*65 + lc + 0] = pv.x; Ps[r*65 + lc + 1] = pv.y;
        Ps[r*65 + lc + 2] = pv.z; Ps[r*65 + lc + 3] = pv.w;
    }
    __syncthreads();

    float acc[4][4];
#pragma unroll
    for (int i = 0; i < 4; i++)
#pragma unroll
        for (int j = 0; j < 4; j++) acc[i][j] = 0.f;

#pragma unroll 4
    for (int d = 0; d < 64; d++) {
        float av[4], bv[4];
#pragma unroll
        for (int i = 0; i < 4; i++) av[i] = Qs[(ty4 + i)*65 + d];
#pragma unroll
        for (int j = 0; j < 4; j++) bv[j] = Ps[(tx + j*16)*65 + d];
#pragma unroll
        for (int i = 0; i < 4; i++)
#pragma unroll
            for (int j = 0; j < 4; j++)
                acc[i][j] = fmaf(av[i], bv[j], acc[i][j]);
    }

    float* Ao = Ag0 + (size_t)bh * S_ * S_;
#pragma unroll
    for (int i = 0; i < 4; i++)
#pragma unroll
        for (int j = 0; j < 4; j++)
            Ao[(size_t)(i0 + ty4 + i)*S_ + k0 + tx + j*16] = acc[i][j];
}

// ---------------------------------------------------------------------------
// Fused flash attention with relative-shift gather from A.
// scores[i,j] = ((Q_i+u)·K_j + shift(A)[i,j]) * SCALE; online softmax; O=p@V.
// smem: Qs[64][65] + KP[64][65] + Vs[64][64] = 49664 B (needs attr bump).
// ---------------------------------------------------------------------------
__global__ __launch_bounds__(256) void flash_kernel(
    const float* __restrict__ Qg0, const float* __restrict__ Kg0,
    const float* __restrict__ Vg0, const float* __restrict__ Ag0,
    const float* __restrict__ u_bias, float* __restrict__ ctx)
{
    extern __shared__ float sm[];
    float* Qs = sm;                    // [64][65]
    float* KP = sm + 64*65;            // [64][65]  (K tile; later reused for p)
    float* Vs = sm + 2*64*65;          // [64][64]

    const int tid = threadIdx.x;
    const int ty4 = (tid >> 4) * 4;
    const int tx  = tid & 15;
    const int it = blockIdx.x, h = blockIdx.y, b = blockIdx.z;
    const int bh = b*H_ + h;
    const int i0 = it * 64;
    const float* Qg = Qg0 + (size_t)bh * S_ * DK_;
    const float* Kg = Kg0 + (size_t)bh * S_ * DK_;
    const float* Vg = Vg0 + (size_t)bh * S_ * DK_;
    const float* Ag = Ag0 + (size_t)bh * S_ * S_;

    const int lr = tid >> 4;
    const int lc = (tid & 15) * 4;
#pragma unroll
    for (int rr = 0; rr < 4; rr++) {
        int r = lr + rr*16;
        float4 qv = *(const float4*)&Qg[(size_t)(i0 + r)*DK_ + lc];
        const float4 ub = *(const float4*)&u_bias[h*DK_ + lc];
        qv.x += ub.x; qv.y += ub.y; qv.z += ub.z; qv.w += ub.w;
        Qs[r*65 + lc + 0] = qv.x; Qs[r*65 + lc + 1] = qv.y;
        Qs[r*65 + lc + 2] = qv.z; Qs[r*65 + lc + 3] = qv.w;
    }

    float m[4], l[4], O[4][4];
#pragma unroll
    for (int i = 0; i < 4; i++) {
        m[i] = -3.0e38f; l[i] = 0.f;
#pragma unroll
        for (int j = 0; j < 4; j++) O[i][j] = 0.f;
    }

    for (int jt = 0; jt < S_/64; jt++) {
        const int j0 = jt * 64;
        __syncthreads();   // prior-iter KP/Vs reads done; covers Qs stores @jt=0
#pragma unroll
        for (int rr = 0; rr < 4; rr++) {
            int r = lr + rr*16;
            float4 kv = *(const float4*)&Kg[(size_t)(j0 + r)*DK_ + lc];
            KP[r*65 + lc + 0] = kv.x; KP[r*65 + lc + 1] = kv.y;
            KP[r*65 + lc + 2] = kv.z; KP[r*65 + lc + 3] = kv.w;
            *(float4*)&Vs[r*64 + lc] =
                *(const float4*)&Vg[(size_t)(j0 + r)*DK_ + lc];
        }
        __syncthreads();

        // ---- content scores: (Q+u) . K ----
        float acc[4][4];
#pragma unroll
        for (int i = 0; i < 4; i++)
#pragma unroll
            for (int j = 0; j < 4; j++) acc[i][j] = 0.f;
#pragma unroll 4
        for (int d = 0; d < 64; d++) {
            float av[4], bv[4];
#pragma unroll
            for (int i = 0; i < 4; i++) av[i] = Qs[(ty4 + i)*65 + d];
#pragma unroll
            for (int j = 0; j < 4; j++) bv[j] = KP[(tx + j*16)*65 + d];
#pragma unroll
            for (int i = 0; i < 4; i++)
#pragma unroll
                for (int j = 0; j < 4; j++)
                    acc[i][j] = fmaf(av[i], bv[j], acc[i][j]);
        }

        // ---- add shifted pos score, online softmax ----
        float p[4][4];
#pragma unroll
        for (int i = 0; i < 4; i++) {
            const int gi = i0 + ty4 + i;
            float rmax = -3.0e38f;
#pragma unroll
            for (int jj = 0; jj < 4; jj++) {
                const int gj = j0 + tx + jj*16;
                float a;
                if (gj <= gi)          a = Ag[(size_t)gi*S_ + (S_-1 - gi + gj)];
                else if (gj == gi + 1) a = 0.f;
                else                   a = Ag[(size_t)(gi+1)*S_ + (gj - gi - 2)];
                float s = (acc[i][jj] + a) * SCALE_;
                p[i][jj] = s;
                rmax = fmaxf(rmax, s);
            }
#pragma unroll
            for (int o = 8; o >= 1; o >>= 1)
                rmax = fmaxf(rmax, __shfl_xor_sync(0xffffffffu, rmax, o));
            const float mnew  = fmaxf(m[i], rmax);
            const float alpha = __expf(m[i] - mnew);
            float rsum = 0.f;
#pragma unroll
            for (int jj = 0; jj < 4; jj++) {
                float e = __expf(p[i][jj] - mnew);
                p[i][jj] = e;
                rsum += e;
            }
#pragma unroll
            for (int o = 8; o >= 1; o >>= 1)
                rsum += __shfl_xor_sync(0xffffffffu, rsum, o);
            l[i] = l[i]*alpha + rsum;
            m[i] = mnew;
#pragma unroll
            for (int j = 0; j < 4; j++) O[i][j] *= alpha;
        }

        __syncthreads();   // all K reads done before overwriting KP with p
#pragma unroll
        for (int i = 0; i < 4; i++)
#pragma unroll
            for (int jj = 0; jj < 4; jj++)
                KP[(ty4 + i)*65 + tx + jj*16] = p[i][jj];
        __syncthreads();

        // ---- O += p @ V ----
#pragma unroll 4
        for (int j = 0; j < 64; j++) {
            float av[4];
#pragma unroll
            for (int i = 0; i < 4; i++) av[i] = KP[(ty4 + i)*65 + j];
            const float4 b4 = *(const float4*)&Vs[j*64 + tx*4];
            const float bv[4] = {b4.x, b4.y, b4.z, b4.w};
#pragma unroll
            for (int i = 0; i < 4; i++)
#pragma unroll
                for (int jd = 0; jd < 4; jd++)
                    O[i][jd] = fmaf(av[i], bv[jd], O[i][jd]);
        }
    }

    // epilogue: normalize, write context as [B,S,H*DK]
#pragma unroll
    for (int i = 0; i < 4; i++) {
        const int gi = i0 + ty4 + i;
        const float inv = 1.0f / l[i];
        float4 o4 = make_float4(O[i][0]*inv, O[i][1]*inv, O[i][2]*inv, O[i][3]*inv);
        *(float4*)&ctx[((size_t)b*S_ + gi)*DM_ + h*DK_ + tx*4] = o4;
    }
}

// ---------------------------------------------------------------------------
extern "C" void kernel_launch(void* const* d_in, const int* in_sizes, int n_in,
                              void* d_out, int out_size)
{
    (void)in_sizes; (void)n_in; (void)out_size;
    const float* inputs  = (const float*)d_in[0];
    const float* pos_enc = (const float*)d_in[1];
    const float* W_q     = (const float*)d_in[2];
    const float* W_k     = (const float*)d_in[3];
    const float* W_v     = (const float*)d_in[4];
    const float* W_o     = (const float*)d_in[5];
    const float* W_pos   = (const float*)d_in[6];
    const float* u_b     = (const float*)d_in[7];
    const float* v_b     = (const float*)d_in[8];
    float* out = (float*)d_out;

    float *qp, *kp, *vp, *pp, *ap, *cp;
    cudaGetSymbolAddress((void**)&qp, g_Q);
    cudaGetSymbolAddress((void**)&kp, g_K);
    cudaGetSymbolAddress((void**)&vp, g_V);
    cudaGetSymbolAddress((void**)&pp, g_P);
    cudaGetSymbolAddress((void**)&ap, g_A);
    cudaGetSymbolAddress((void**)&cp, g_ctx);

    const int FLASH_SMEM = (2*64*65 + 64*64) * (int)sizeof(float);  // 49664 B
    cudaFuncSetAttribute(flash_kernel,
                         cudaFuncAttributeMaxDynamicSharedMemorySize, FLASH_SMEM);

    const dim3 thr(256);
    // projections (head-split layout)
    gemm512_kernel<1><<<dim3(128, 8), thr>>>(inputs,  W_q,   qp);
    gemm512_kernel<1><<<dim3(128, 8), thr>>>(inputs,  W_k,   kp);
    gemm512_kernel<1><<<dim3(128, 8), thr>>>(inputs,  W_v,   vp);
    gemm512_kernel<1><<<dim3(32,  8), thr>>>(pos_enc, W_pos, pp);
    // pos matrix A = (Q+v) @ P^T per (b,h)
    posA_kernel<<<dim3(32, 32, 32), thr>>>(qp, pp, v_b, ap);
    // fused attention -> g_ctx
    flash_kernel<<<dim3(32, 8, 4), thr, FLASH_SMEM>>>(qp, kp, vp, ap, u_b, cp);
    // output projection: ctx @ W_o -> out
    gemm512_kernel<0><<<dim3(128, 8), thr>>>(cp, W_o, out);
}

// round 4
// speedup vs baseline: 1.1088x; 1.1088x over previous
#include <cuda_runtime.h>

#define B_  4
#define S_  2048
#define DM_ 512
#define H_  8
#define DK_ 64
#define SCALE_ 0.125f

typedef unsigned long long u64;

// ---- packed fp32x2 helpers (Blackwell f32x2 pipe: 2 FMAs per fma-slot) ----
__device__ __forceinline__ void fma2(u64 &c, u64 a, u64 b) {
    asm("fma.rn.f32x2 %0, %1, %2, %0;" : "+l"(c) : "l"(a), "l"(b));
}
__device__ __forceinline__ u64 mul2(u64 a, u64 b) {
    u64 r; asm("mul.rn.f32x2 %0, %1, %2;" : "=l"(r) : "l"(a), "l"(b)); return r;
}
__device__ __forceinline__ u64 dup2(float a) {
    u64 r; asm("mov.b64 %0, {%1, %1};" : "=l"(r) : "f"(a)); return r;
}
__device__ __forceinline__ float2 unp(u64 v) {
    float2 f; asm("mov.b64 {%0, %1}, %2;" : "=f"(f.x), "=f"(f.y) : "l"(v)); return f;
}

// ---------------- scratch (device globals: allocation-free rule) -------------
__device__ float g_Q[B_*H_*S_*DK_];            // [B,H,S,DK]
__device__ float g_K[B_*H_*S_*DK_];
__device__ float g_V[B_*H_*S_*DK_];
__device__ float g_P[H_*S_*DK_];               // [H,S,DK]
__device__ float g_A[(size_t)B_*H_*S_*S_];     // pos matrix before shift [BH,S,S]
__device__ float g_ctx[B_*S_*DM_];             // attention output, [B,S,DM]

// ---------------------------------------------------------------------------
// C = X[M,512] @ W[512,512].  64x128 tile, 256 thr, 4x8 per thread (f32x2).
// SPLIT=1: head-split layout out[((b*H+h)*S+s)*DK+d]; SPLIT=0: row-major.
// ---------------------------------------------------------------------------
template<int SPLIT>
__global__ __launch_bounds__(256) void gemm512_kernel(
    const float* __restrict__ X, const float* __restrict__ W,
    float* __restrict__ out)
{
    __shared__ float2 As2[64*17];     // duplicated a-operand (broadcast LDS.64)
    __shared__ float  Bs[16*128];
    const int tid = threadIdx.x;
    const int ty4 = (tid >> 4) * 4;
    const int tx  = tid & 15;
    const int m0 = blockIdx.x * 64;
    const int n0 = blockIdx.y * 128;

    u64 acc[4][4];
#pragma unroll
    for (int i = 0; i < 4; i++)
#pragma unroll
        for (int j = 0; j < 4; j++) acc[i][j] = 0ull;

    for (int k0 = 0; k0 < 512; k0 += 16) {
        {   // A tile 64x16, duplicated
            int r = tid >> 2, c = (tid & 3) * 4;
            float4 a4 = *(const float4*)&X[(size_t)(m0 + r)*512 + k0 + c];
            As2[r*17 + c + 0] = make_float2(a4.x, a4.x);
            As2[r*17 + c + 1] = make_float2(a4.y, a4.y);
            As2[r*17 + c + 2] = make_float2(a4.z, a4.z);
            As2[r*17 + c + 3] = make_float2(a4.w, a4.w);
        }
        {   // B tile 16x128
            int r = tid >> 4, c = tx * 8;
            const float* wr = &W[(size_t)(k0 + r)*512 + n0 + c];
            *(float4*)&Bs[r*128 + c]     = *(const float4*)&wr[0];
            *(float4*)&Bs[r*128 + c + 4] = *(const float4*)&wr[4];
        }
        __syncthreads();
#pragma unroll
        for (int kk = 0; kk < 16; kk++) {
            u64 av[4], bv[4];
#pragma unroll
            for (int i = 0; i < 4; i++)
                av[i] = *(const u64*)&As2[(ty4 + i)*17 + kk];
#pragma unroll
            for (int j = 0; j < 4; j++)
                bv[j] = *(const u64*)&Bs[kk*128 + j*32 + tx*2];
#pragma unroll
            for (int i = 0; i < 4; i++)
#pragma unroll
                for (int j = 0; j < 4; j++)
                    fma2(acc[i][j], av[i], bv[j]);
        }
        __syncthreads();
    }

#pragma unroll
    for (int i = 0; i < 4; i++) {
        const int mm = m0 + ty4 + i;
#pragma unroll
        for (int j = 0; j < 4; j++) {
            const int nn = n0 + j*32 + tx*2;
            float2 v = unp(acc[i][j]);
            if (SPLIT) {
                int bb = mm >> 11, ss = mm & 2047;
                int hh = nn >> 6,  dd = nn & 63;
                *(float2*)&out[((size_t)(bb*H_ + hh)*S_ + ss)*DK_ + dd] = v;
            } else {
                *(float2*)&out[(size_t)mm*512 + nn] = v;
            }
        }
    }
}

// ---------------------------------------------------------------------------
// A[bh,i,k] = sum_d (Q[bh,i,d]+v_bias[h,d]) * P[h,k,d]. 64x128 tile, K=64.
// smem: Qdup (float2, stride 65) + Pt transposed [d][k] (stride 130).
// ---------------------------------------------------------------------------
__global__ __launch_bounds__(256) void posA_kernel(
    const float* __restrict__ Qg0, const float* __restrict__ Pg0,
    const float* __restrict__ v_bias, float* __restrict__ Ag0)
{
    extern __shared__ float sm[];
    float2* Qd = (float2*)sm;          // [64*65] float2
    float*  Pt = sm + 2*64*65;         // [64*130]

    const int tid = threadIdx.x;
    const int ty4 = (tid >> 4) * 4;
    const int tx  = tid & 15;
    const int k0 = blockIdx.x * 128;
    const int i0 = blockIdx.y * 64;
    const int bh = blockIdx.z;
    const int h  = bh & 7;
    const float* Qg = Qg0 + (size_t)bh * S_ * DK_;
    const float* Pg = Pg0 + (size_t)h  * S_ * DK_;

    const int lr = tid >> 4;
    const int lc = tx * 4;
#pragma unroll
    for (int rr = 0; rr < 4; rr++) {      // Q rows 0..63, duplicated
        int r = lr + rr*16;
        float4 qv = *(const float4*)&Qg[(size_t)(i0 + r)*DK_ + lc];
        const float4 vb = *(const float4*)&v_bias[h*DK_ + lc];
        qv.x += vb.x; qv.y += vb.y; qv.z += vb.z; qv.w += vb.w;
        Qd[r*65 + lc + 0] = make_float2(qv.x, qv.x);
        Qd[r*65 + lc + 1] = make_float2(qv.y, qv.y);
        Qd[r*65 + lc + 2] = make_float2(qv.z, qv.z);
        Qd[r*65 + lc + 3] = make_float2(qv.w, qv.w);
    }
#pragma unroll
    for (int rr = 0; rr < 8; rr++) {      // P rows 0..127, transposed [d][k]
        int r = lr + rr*16;
        float4 pv = *(const float4*)&Pg[(size_t)(k0 + r)*DK_ + lc];
        Pt[(lc + 0)*130 + r] = pv.x;
        Pt[(lc + 1)*130 + r] = pv.y;
        Pt[(lc + 2)*130 + r] = pv.z;
        Pt[(lc + 3)*130 + r] = pv.w;
    }
    __syncthreads();

    u64 acc[4][4];
#pragma unroll
    for (int i = 0; i < 4; i++)
#pragma unroll
        for (int j = 0; j < 4; j++) acc[i][j] = 0ull;

#pragma unroll 4
    for (int d = 0; d < 64; d++) {
        u64 av[4], bv[4];
#pragma unroll
        for (int i = 0; i < 4; i++)
            av[i] = *(const u64*)&Qd[(ty4 + i)*65 + d];
#pragma unroll
        for (int j = 0; j < 4; j++)
            bv[j] = *(const u64*)&Pt[d*130 + j*32 + tx*2];
#pragma unroll
        for (int i = 0; i < 4; i++)
#pragma unroll
            for (int j = 0; j < 4; j++)
                fma2(acc[i][j], av[i], bv[j]);
    }

    float* Ao = Ag0 + (size_t)bh * S_ * S_;
#pragma unroll
    for (int i = 0; i < 4; i++)
#pragma unroll
        for (int j = 0; j < 4; j++) {
            float2 v = unp(acc[i][j]);
            *(float2*)&Ao[(size_t)(i0 + ty4 + i)*S_ + k0 + j*32 + tx*2] = v;
        }
}

// ---------------------------------------------------------------------------
// Fused flash attention. BM=64, BN=128 per iter, f32x2 throughout.
// scores[i,j] = ((Q_i+u)·K_j + shift(A)[i,j]) * SCALE; online softmax; O=p@V.
// shift(A)[i,j] = A[i,S-1-i+j] (j<=i); 0 (j==i+1); A[i+1,j-i-2] (j>=i+2).
// smem: Qdup 33280 + union(Kt|Pp) 33280 + Vs 32768 = 99328 B.
// ---------------------------------------------------------------------------
__global__ __launch_bounds__(256, 2) void flash_kernel(
    const float* __restrict__ Qg0, const float* __restrict__ Kg0,
    const float* __restrict__ Vg0, const float* __restrict__ Ag0,
    const float* __restrict__ u_bias, float* __restrict__ ctx)
{
    extern __shared__ float sm[];
    float2* Qd = (float2*)sm;          // [64*65] float2  (duplicated Q+u)
    float*  U  = sm + 2*64*65;         // [64*130] union: Kt [d][col] / Pp [row][col]
    float*  Vs = U + 64*130;           // [128*64]

    const int tid = threadIdx.x;
    const int ty4 = (tid >> 4) * 4;
    const int tx  = tid & 15;
    const int i0 = blockIdx.x * 64;
    const int h = blockIdx.y, b = blockIdx.z;
    const int bh = b*H_ + h;
    const float* Qg = Qg0 + (size_t)bh * S_ * DK_;
    const float* Kg = Kg0 + (size_t)bh * S_ * DK_;
    const float* Vg = Vg0 + (size_t)bh * S_ * DK_;
    const float* Ag = Ag0 + (size_t)bh * S_ * S_;

    const int lr = tid >> 4;
    const int lc = tx * 4;
#pragma unroll
    for (int rr = 0; rr < 4; rr++) {
        int r = lr + rr*16;
        float4 qv = *(const float4*)&Qg[(size_t)(i0 + r)*DK_ + lc];
        const float4 ub = *(const float4*)&u_bias[h*DK_ + lc];
        qv.x += ub.x; qv.y += ub.y; qv.z += ub.z; qv.w += ub.w;
        Qd[r*65 + lc + 0] = make_float2(qv.x, qv.x);
        Qd[r*65 + lc + 1] = make_float2(qv.y, qv.y);
        Qd[r*65 + lc + 2] = make_float2(qv.z, qv.z);
        Qd[r*65 + lc + 3] = make_float2(qv.w, qv.w);
    }

    float m[4], l[4];
    u64 O[4][2];
#pragma unroll
    for (int i = 0; i < 4; i++) {
        m[i] = -3.0e38f; l[i] = 0.f;
        O[i][0] = 0ull; O[i][1] = 0ull;
    }

    for (int jt = 0; jt < S_/128; jt++) {
        const int j0 = jt * 128;
        __syncthreads();   // previous iter's U/Vs reads complete
#pragma unroll
        for (int rr = 0; rr < 8; rr++) {   // K transposed, V row-major
            int r = lr + rr*16;
            float4 kv = *(const float4*)&Kg[(size_t)(j0 + r)*DK_ + lc];
            U[(lc + 0)*130 + r] = kv.x;
            U[(lc + 1)*130 + r] = kv.y;
            U[(lc + 2)*130 + r] = kv.z;
            U[(lc + 3)*130 + r] = kv.w;
            *(float4*)&Vs[r*64 + lc] =
                *(const float4*)&Vg[(size_t)(j0 + r)*DK_ + lc];
        }
        __syncthreads();

        // ---- content scores: (Q+u) . K ----
        u64 acc[4][4];
#pragma unroll
        for (int i = 0; i < 4; i++)
#pragma unroll
            for (int j = 0; j < 4; j++) acc[i][j] = 0ull;
#pragma unroll 4
        for (int d = 0; d < 64; d++) {
            u64 av[4], bv[4];
#pragma unroll
            for (int i = 0; i < 4; i++)
                av[i] = *(const u64*)&Qd[(ty4 + i)*65 + d];
#pragma unroll
            for (int j = 0; j < 4; j++)
                bv[j] = *(const u64*)&U[d*130 + j*32 + tx*2];
#pragma unroll
            for (int i = 0; i < 4; i++)
#pragma unroll
                for (int j = 0; j < 4; j++)
                    fma2(acc[i][j], av[i], bv[j]);
        }

        // ---- add shifted pos score, online softmax ----
        float ps[4][8];
#pragma unroll
        for (int i = 0; i < 4; i++) {
            const int gi = i0 + ty4 + i;
            float rmax = -3.0e38f;
#pragma unroll
            for (int j = 0; j < 4; j++) {
                float2 sc = unp(acc[i][j]);
                const int c0 = j0 + j*32 + tx*2;
#pragma unroll
                for (int q = 0; q < 2; q++) {
                    const int gj = c0 + q;
                    float a;
                    if (gj <= gi)          a = Ag[(size_t)gi*S_ + (S_-1 - gi + gj)];
                    else if (gj == gi + 1) a = 0.f;
                    else                   a = Ag[(size_t)(gi+1)*S_ + (gj - gi - 2)];
                    float s = ((q ? sc.y : sc.x) + a) * SCALE_;
                    ps[i][j*2 + q] = s;
                    rmax = fmaxf(rmax, s);
                }
            }
#pragma unroll
            for (int o = 8; o >= 1; o >>= 1)
                rmax = fmaxf(rmax, __shfl_xor_sync(0xffffffffu, rmax, o));
            const float mnew  = fmaxf(m[i], rmax);
            const float alpha = __expf(m[i] - mnew);
            float rsum = 0.f;
#pragma unroll
            for (int jj = 0; jj < 8; jj++) {
                float e = __expf(ps[i][jj] - mnew);
                ps[i][jj] = e;
                rsum += e;
            }
#pragma unroll
            for (int o = 8; o >= 1; o >>= 1)
                rsum += __shfl_xor_sync(0xffffffffu, rsum, o);
            l[i] = l[i]*alpha + rsum;
            m[i] = mnew;
            const u64 al = dup2(alpha);
            O[i][0] = mul2(O[i][0], al);
            O[i][1] = mul2(O[i][1], al);
        }

        __syncthreads();   // all Kt reads done before overwriting U with p
#pragma unroll
        for (int i = 0; i < 4; i++)
#pragma unroll
            for (int j = 0; j < 4; j++)
                *(float2*)&U[(ty4 + i)*130 + j*32 + tx*2] =
                    make_float2(ps[i][j*2], ps[i][j*2 + 1]);
        __syncthreads();

        // ---- O += p @ V ----
#pragma unroll 2
        for (int j = 0; j < 128; j++) {
            u64 a2[4];
#pragma unroll
            for (int i = 0; i < 4; i++)
                a2[i] = dup2(U[(ty4 + i)*130 + j]);
            u64 bv0 = *(const u64*)&Vs[j*64 + tx*2];
            u64 bv1 = *(const u64*)&Vs[j*64 + 32 + tx*2];
#pragma unroll
            for (int i = 0; i < 4; i++) {
                fma2(O[i][0], a2[i], bv0);
                fma2(O[i][1], a2[i], bv1);
            }
        }
    }

    // epilogue: normalize, write context as [B,S,H*DK]
#pragma unroll
    for (int i = 0; i < 4; i++) {
        const int gi = i0 + ty4 + i;
        const float inv = 1.0f / l[i];
        float2 o0 = unp(O[i][0]); o0.x *= inv; o0.y *= inv;
        float2 o1 = unp(O[i][1]); o1.x *= inv; o1.y *= inv;
        float* dst = &ctx[((size_t)b*S_ + gi)*DM_ + h*DK_];
        *(float2*)&dst[tx*2]      = o0;
        *(float2*)&dst[32 + tx*2] = o1;
    }
}

// ---------------------------------------------------------------------------
extern "C" void kernel_launch(void* const* d_in, const int* in_sizes, int n_in,
                              void* d_out, int out_size)
{
    (void)in_sizes; (void)n_in; (void)out_size;
    const float* inputs  = (const float*)d_in[0];
    const float* pos_enc = (const float*)d_in[1];
    const float* W_q     = (const float*)d_in[2];
    const float* W_k     = (const float*)d_in[3];
    const float* W_v     = (const float*)d_in[4];
    const float* W_o     = (const float*)d_in[5];
    const float* W_pos   = (const float*)d_in[6];
    const float* u_b     = (const float*)d_in[7];
    const float* v_b     = (const float*)d_in[8];
    float* out = (float*)d_out;

    float *qp, *kp, *vp, *pp, *ap, *cp;
    cudaGetSymbolAddress((void**)&qp, g_Q);
    cudaGetSymbolAddress((void**)&kp, g_K);
    cudaGetSymbolAddress((void**)&vp, g_V);
    cudaGetSymbolAddress((void**)&pp, g_P);
    cudaGetSymbolAddress((void**)&ap, g_A);
    cudaGetSymbolAddress((void**)&cp, g_ctx);

    const int POSA_SMEM  = (2*64*65 + 64*130) * (int)sizeof(float);            // 66560
    const int FLASH_SMEM = (2*64*65 + 64*130 + 128*64) * (int)sizeof(float);   // 99328
    cudaFuncSetAttribute(posA_kernel,
                         cudaFuncAttributeMaxDynamicSharedMemorySize, POSA_SMEM);
    cudaFuncSetAttribute(flash_kernel,
                         cudaFuncAttributeMaxDynamicSharedMemorySize, FLASH_SMEM);

    const dim3 thr(256);
    // projections (head-split layout)
    gemm512_kernel<1><<<dim3(128, 4), thr>>>(inputs,  W_q,   qp);
    gemm512_kernel<1><<<dim3(128, 4), thr>>>(inputs,  W_k,   kp);
    gemm512_kernel<1><<<dim3(128, 4), thr>>>(inputs,  W_v,   vp);
    gemm512_kernel<1><<<dim3(32,  4), thr>>>(pos_enc, W_pos, pp);
    // pos matrix A = (Q+v) @ P^T per (b,h)
    posA_kernel<<<dim3(16, 32, 32), thr, POSA_SMEM>>>(qp, pp, v_b, ap);
    // fused attention -> g_ctx
    flash_kernel<<<dim3(32, 8, 4), thr, FLASH_SMEM>>>(qp, kp, vp, ap, u_b, cp);
    // output projection: ctx @ W_o -> out
    gemm512_kernel<0><<<dim3(128, 4), thr>>>(cp, W_o, out);
}

// round 5
// speedup vs baseline: 1.1517x; 1.0387x over previous
#include <cuda_runtime.h>

#define B_  4
#define S_  2048
#define DM_ 512
#define H_  8
#define DK_ 64
#define SCALE_ 0.125f

typedef unsigned long long u64;

// ---- packed fp32x2 helpers (FFMA2: 2 fp32 FMAs per fma-pipe slot) ----
__device__ __forceinline__ void fma2(u64 &c, u64 a, u64 b) {
    asm("fma.rn.f32x2 %0, %1, %2, %0;" : "+l"(c) : "l"(a), "l"(b));
}
__device__ __forceinline__ u64 mul2(u64 a, u64 b) {
    u64 r; asm("mul.rn.f32x2 %0, %1, %2;" : "=l"(r) : "l"(a), "l"(b)); return r;
}
__device__ __forceinline__ u64 dup2(float a) {
    u64 r; asm("mov.b64 %0, {%1, %1};" : "=l"(r) : "f"(a)); return r;
}
__device__ __forceinline__ float2 unp(u64 v) {
    float2 f; asm("mov.b64 {%0, %1}, %2;" : "=f"(f.x), "=f"(f.y) : "l"(v)); return f;
}

// ---------------- scratch (device globals: allocation-free rule) -------------
__device__ float g_Q[B_*H_*S_*DK_];            // [B,H,S,DK]
__device__ float g_K[B_*H_*S_*DK_];
__device__ float g_V[B_*H_*S_*DK_];
__device__ float g_P[H_*S_*DK_];               // [H,S,DK]
__device__ float g_A[(size_t)B_*H_*S_*S_];     // pos matrix before shift [BH,S,S]
__device__ float g_ctx[B_*S_*DM_];             // attention output, [B,S,DM]

// ---------------------------------------------------------------------------
// C = X[M,512] @ W[512,512].  64x128 tile, 256 thr, 4x8 outputs (f32x2).
// Double-buffered smem (1 sync per k-iter, LDG overlapped with FFMA2).
// SPLIT=1: head-split layout out[((b*H+h)*S+s)*DK+d]; SPLIT=0: row-major.
// ---------------------------------------------------------------------------
template<int SPLIT>
__global__ __launch_bounds__(256, 3) void gemm512_kernel(
    const float* __restrict__ X, const float* __restrict__ W,
    float* __restrict__ out)
{
    __shared__ float2 As2[2][64*17];   // duplicated a-operand (broadcast LDS.64)
    __shared__ float  Bs[2][16*128];
    const int tid = threadIdx.x;
    const int ty4 = (tid >> 4) * 4;
    const int tx  = tid & 15;
    const int m0 = blockIdx.x * 64;
    const int n0 = blockIdx.y * 128;
    const int ar = tid >> 2, ac = (tid & 3) * 4;
    const int br = tid >> 4, bc = (tid & 15) * 8;
    const float* Xp = &X[(size_t)(m0 + ar)*512 + ac];
    const float* Wp = &W[(size_t)br*512 + n0 + bc];

    u64 acc[4][4];
#pragma unroll
    for (int i = 0; i < 4; i++)
#pragma unroll
        for (int j = 0; j < 4; j++) acc[i][j] = 0ull;

    // prologue: load k-tile 0 into buffer 0
    {
        float4 a4  = *(const float4*)Xp;
        float4 b40 = *(const float4*)&Wp[0];
        float4 b41 = *(const float4*)&Wp[4];
        As2[0][ar*17 + ac + 0] = make_float2(a4.x, a4.x);
        As2[0][ar*17 + ac + 1] = make_float2(a4.y, a4.y);
        As2[0][ar*17 + ac + 2] = make_float2(a4.z, a4.z);
        As2[0][ar*17 + ac + 3] = make_float2(a4.w, a4.w);
        *(float4*)&Bs[0][br*128 + bc]     = b40;
        *(float4*)&Bs[0][br*128 + bc + 4] = b41;
    }
    __syncthreads();

    for (int k0 = 0; k0 < 32; k0++) {
        const int cur = k0 & 1;
        float4 na, nb0, nb1;
        if (k0 < 31) {   // prefetch next k-tile (global) before compute
            na  = *(const float4*)(Xp + (k0 + 1)*16);
            nb0 = *(const float4*)(Wp + (size_t)(k0 + 1)*16*512);
            nb1 = *(const float4*)(Wp + (size_t)(k0 + 1)*16*512 + 4);
        }
#pragma unroll
        for (int kk = 0; kk < 16; kk++) {
            u64 av[4], bv[4];
#pragma unroll
            for (int i = 0; i < 4; i++)
                av[i] = *(const u64*)&As2[cur][(ty4 + i)*17 + kk];
#pragma unroll
            for (int j = 0; j < 4; j++)
                bv[j] = *(const u64*)&Bs[cur][kk*128 + j*32 + tx*2];
#pragma unroll
            for (int i = 0; i < 4; i++)
#pragma unroll
                for (int j = 0; j < 4; j++)
                    fma2(acc[i][j], av[i], bv[j]);
        }
        if (k0 < 31) {   // stage next tile into the other buffer
            const int nxt = cur ^ 1;
            As2[nxt][ar*17 + ac + 0] = make_float2(na.x, na.x);
            As2[nxt][ar*17 + ac + 1] = make_float2(na.y, na.y);
            As2[nxt][ar*17 + ac + 2] = make_float2(na.z, na.z);
            As2[nxt][ar*17 + ac + 3] = make_float2(na.w, na.w);
            *(float4*)&Bs[nxt][br*128 + bc]     = nb0;
            *(float4*)&Bs[nxt][br*128 + bc + 4] = nb1;
        }
        __syncthreads();
    }

#pragma unroll
    for (int i = 0; i < 4; i++) {
        const int mm = m0 + ty4 + i;
#pragma unroll
        for (int j = 0; j < 4; j++) {
            const int nn = n0 + j*32 + tx*2;
            float2 v = unp(acc[i][j]);
            if (SPLIT) {
                int bb = mm >> 11, ss = mm & 2047;
                int hh = nn >> 6,  dd = nn & 63;
                *(float2*)&out[((size_t)(bb*H_ + hh)*S_ + ss)*DK_ + dd] = v;
            } else {
                *(float2*)&out[(size_t)mm*512 + nn] = v;
            }
        }
    }
}

// ---------------------------------------------------------------------------
// A[bh,i,k] = sum_d (Q[bh,i,d]+v_bias[h,d]) * P[h,k,d]. 64x128 tile, K=64.
// smem: Qdup (float2, stride 65) + Pt transposed [d][k] (stride 130). 66.5KB.
// ---------------------------------------------------------------------------
__global__ __launch_bounds__(256, 3) void posA_kernel(
    const float* __restrict__ Qg0, const float* __restrict__ Pg0,
    const float* __restrict__ v_bias, float* __restrict__ Ag0)
{
    extern __shared__ float sm[];
    float2* Qd = (float2*)sm;          // [64*65] float2
    float*  Pt = sm + 2*64*65;         // [64*130]

    const int tid = threadIdx.x;
    const int ty4 = (tid >> 4) * 4;
    const int tx  = tid & 15;
    const int k0 = blockIdx.x * 128;
    const int i0 = blockIdx.y * 64;
    const int bh = blockIdx.z;
    const int h  = bh & 7;
    const float* Qg = Qg0 + (size_t)bh * S_ * DK_;
    const float* Pg = Pg0 + (size_t)h  * S_ * DK_;

    const int lr = tid >> 4;
    const int lc = tx * 4;
#pragma unroll
    for (int rr = 0; rr < 4; rr++) {      // Q rows 0..63, duplicated
        int r = lr + rr*16;
        float4 qv = *(const float4*)&Qg[(size_t)(i0 + r)*DK_ + lc];
        const float4 vb = *(const float4*)&v_bias[h*DK_ + lc];
        qv.x += vb.x; qv.y += vb.y; qv.z += vb.z; qv.w += vb.w;
        Qd[r*65 + lc + 0] = make_float2(qv.x, qv.x);
        Qd[r*65 + lc + 1] = make_float2(qv.y, qv.y);
        Qd[r*65 + lc + 2] = make_float2(qv.z, qv.z);
        Qd[r*65 + lc + 3] = make_float2(qv.w, qv.w);
    }
#pragma unroll
    for (int rr = 0; rr < 8; rr++) {      // P rows 0..127, transposed [d][k]
        int r = lr + rr*16;
        float4 pv = *(const float4*)&Pg[(size_t)(k0 + r)*DK_ + lc];
        Pt[(lc + 0)*130 + r] = pv.x;
        Pt[(lc + 1)*130 + r] = pv.y;
        Pt[(lc + 2)*130 + r] = pv.z;
        Pt[(lc + 3)*130 + r] = pv.w;
    }
    __syncthreads();

    u64 acc[4][4];
#pragma unroll
    for (int i = 0; i < 4; i++)
#pragma unroll
        for (int j = 0; j < 4; j++) acc[i][j] = 0ull;

#pragma unroll 4
    for (int d = 0; d < 64; d++) {
        u64 av[4], bv[4];
#pragma unroll
        for (int i = 0; i < 4; i++)
            av[i] = *(const u64*)&Qd[(ty4 + i)*65 + d];
#pragma unroll
        for (int j = 0; j < 4; j++)
            bv[j] = *(const u64*)&Pt[d*130 + j*32 + tx*2];
#pragma unroll
        for (int i = 0; i < 4; i++)
#pragma unroll
            for (int j = 0; j < 4; j++)
                fma2(acc[i][j], av[i], bv[j]);
    }

    float* Ao = Ag0 + (size_t)bh * S_ * S_;
#pragma unroll
    for (int i = 0; i < 4; i++)
#pragma unroll
        for (int j = 0; j < 4; j++) {
            float2 v = unp(acc[i][j]);
            *(float2*)&Ao[(size_t)(i0 + ty4 + i)*S_ + k0 + j*32 + tx*2] = v;
        }
}

// ---------------------------------------------------------------------------
// Fused flash attention. BM=64, BN=128 per iter, f32x2 throughout.
// scores[i,j] = ((Q_i+u)·K_j + shift(A)[i,j]) * SCALE; online softmax; O=p@V.
// shift(A)[i,j] -> unified gather index gi*(S-1)+gj+(gj<=gi+1 ? S-1 : S-2),
// with a zero-select on the j==i+1 diagonal.  A loads are prefetched BEFORE
// the score GEMM so their DRAM latency is hidden under ~64 FFMA2 iterations.
// smem: Qdup 33280 + union(Kt|Pp) 33280 + Vs 32768 = 99328 B (2 blocks/SM).
// ---------------------------------------------------------------------------
__global__ __launch_bounds__(256, 2) void flash_kernel(
    const float* __restrict__ Qg0, const float* __restrict__ Kg0,
    const float* __restrict__ Vg0, const float* __restrict__ Ag0,
    const float* __restrict__ u_bias, float* __restrict__ ctx)
{
    extern __shared__ float sm[];
    float2* Qd = (float2*)sm;          // [64*65] float2  (duplicated Q+u)
    float*  U  = sm + 2*64*65;         // [64*130] union: Kt [d][col] / p [row][col]
    float*  Vs = U + 64*130;           // [128*64]

    const int tid = threadIdx.x;
    const int ty4 = (tid >> 4) * 4;
    const int tx  = tid & 15;
    const int i0 = blockIdx.x * 64;
    const int h = blockIdx.y, b = blockIdx.z;
    const int bh = b*H_ + h;
    const float* Qg = Qg0 + (size_t)bh * S_ * DK_;
    const float* Kg = Kg0 + (size_t)bh * S_ * DK_;
    const float* Vg = Vg0 + (size_t)bh * S_ * DK_;
    const float* Ag = Ag0 + (size_t)bh * S_ * S_;

    const int lr = tid >> 4;
    const int lc = tx * 4;
#pragma unroll
    for (int rr = 0; rr < 4; rr++) {
        int r = lr + rr*16;
        float4 qv = *(const float4*)&Qg[(size_t)(i0 + r)*DK_ + lc];
        const float4 ub = *(const float4*)&u_bias[h*DK_ + lc];
        qv.x += ub.x; qv.y += ub.y; qv.z += ub.z; qv.w += ub.w;
        Qd[r*65 + lc + 0] = make_float2(qv.x, qv.x);
        Qd[r*65 + lc + 1] = make_float2(qv.y, qv.y);
        Qd[r*65 + lc + 2] = make_float2(qv.z, qv.z);
        Qd[r*65 + lc + 3] = make_float2(qv.w, qv.w);
    }

    float m[4], l[4];
    u64 O[4][2];
#pragma unroll
    for (int i = 0; i < 4; i++) {
        m[i] = -3.0e38f; l[i] = 0.f;
        O[i][0] = 0ull; O[i][1] = 0ull;
    }

    for (int jt = 0; jt < S_/128; jt++) {
        const int j0 = jt * 128;
        __syncthreads();   // previous iter's U/Vs reads complete
#pragma unroll
        for (int rr = 0; rr < 8; rr++) {   // K transposed, V row-major
            int r = lr + rr*16;
            float4 kv = *(const float4*)&Kg[(size_t)(j0 + r)*DK_ + lc];
            U[(lc + 0)*130 + r] = kv.x;
            U[(lc + 1)*130 + r] = kv.y;
            U[(lc + 2)*130 + r] = kv.z;
            U[(lc + 3)*130 + r] = kv.w;
            *(float4*)&Vs[r*64 + lc] =
                *(const float4*)&Vg[(size_t)(j0 + r)*DK_ + lc];
        }

        // ---- prefetch shifted-A gather (independent of score GEMM) ----
        float ap[4][8];
#pragma unroll
        for (int i = 0; i < 4; i++) {
            const int gi = i0 + ty4 + i;
            const size_t base = (size_t)gi * (S_ - 1);
#pragma unroll
            for (int j = 0; j < 4; j++)
#pragma unroll
                for (int q = 0; q < 2; q++) {
                    const int gj = j0 + j*32 + tx*2 + q;
                    const size_t idx =
                        base + gj + ((gj <= gi + 1) ? (S_ - 1) : (S_ - 2));
                    float a = __ldg(&Ag[idx]);
                    ap[i][j*2 + q] = (gj == gi + 1) ? 0.f : a;
                }
        }
        __syncthreads();

        // ---- content scores: (Q+u) . K ----
        u64 acc[4][4];
#pragma unroll
        for (int i = 0; i < 4; i++)
#pragma unroll
            for (int j = 0; j < 4; j++) acc[i][j] = 0ull;
#pragma unroll 4
        for (int d = 0; d < 64; d++) {
            u64 av[4], bv[4];
#pragma unroll
            for (int i = 0; i < 4; i++)
                av[i] = *(const u64*)&Qd[(ty4 + i)*65 + d];
#pragma unroll
            for (int j = 0; j < 4; j++)
                bv[j] = *(const u64*)&U[d*130 + j*32 + tx*2];
#pragma unroll
            for (int i = 0; i < 4; i++)
#pragma unroll
                for (int j = 0; j < 4; j++)
                    fma2(acc[i][j], av[i], bv[j]);
        }

        // ---- combine with prefetched pos score, online softmax ----
        float ps[4][8];
#pragma unroll
        for (int i = 0; i < 4; i++) {
            float rmax = -3.0e38f;
#pragma unroll
            for (int j = 0; j < 4; j++) {
                float2 sc = unp(acc[i][j]);
                float s0 = (sc.x + ap[i][j*2])     * SCALE_;
                float s1 = (sc.y + ap[i][j*2 + 1]) * SCALE_;
                ps[i][j*2]     = s0;
                ps[i][j*2 + 1] = s1;
                rmax = fmaxf(rmax, fmaxf(s0, s1));
            }
#pragma unroll
            for (int o = 8; o >= 1; o >>= 1)
                rmax = fmaxf(rmax, __shfl_xor_sync(0xffffffffu, rmax, o));
            const float mnew  = fmaxf(m[i], rmax);
            const float alpha = __expf(m[i] - mnew);
            float rsum = 0.f;
#pragma unroll
            for (int jj = 0; jj < 8; jj++) {
                float e = __expf(ps[i][jj] - mnew);
                ps[i][jj] = e;
                rsum += e;
            }
#pragma unroll
            for (int o = 8; o >= 1; o >>= 1)
                rsum += __shfl_xor_sync(0xffffffffu, rsum, o);
            l[i] = l[i]*alpha + rsum;
            m[i] = mnew;
            const u64 al = dup2(alpha);
            O[i][0] = mul2(O[i][0], al);
            O[i][1] = mul2(O[i][1], al);
        }

        __syncthreads();   // all Kt reads done before overwriting U with p
#pragma unroll
        for (int i = 0; i < 4; i++)
#pragma unroll
            for (int j = 0; j < 4; j++)
                *(float2*)&U[(ty4 + i)*130 + j*32 + tx*2] =
                    make_float2(ps[i][j*2], ps[i][j*2 + 1]);
        __syncthreads();

        // ---- O += p @ V ----
#pragma unroll 2
        for (int j = 0; j < 128; j++) {
            u64 a2[4];
#pragma unroll
            for (int i = 0; i < 4; i++)
                a2[i] = dup2(U[(ty4 + i)*130 + j]);
            u64 bv0 = *(const u64*)&Vs[j*64 + tx*2];
            u64 bv1 = *(const u64*)&Vs[j*64 + 32 + tx*2];
#pragma unroll
            for (int i = 0; i < 4; i++) {
                fma2(O[i][0], a2[i], bv0);
                fma2(O[i][1], a2[i], bv1);
            }
        }
    }

    // epilogue: normalize, write context as [B,S,H*DK]
#pragma unroll
    for (int i = 0; i < 4; i++) {
        const int gi = i0 + ty4 + i;
        const float inv = 1.0f / l[i];
        float2 o0 = unp(O[i][0]); o0.x *= inv; o0.y *= inv;
        float2 o1 = unp(O[i][1]); o1.x *= inv; o1.y *= inv;
        float* dst = &ctx[((size_t)b*S_ + gi)*DM_ + h*DK_];
        *(float2*)&dst[tx*2]      = o0;
        *(float2*)&dst[32 + tx*2] = o1;
    }
}

// ---------------------------------------------------------------------------
extern "C" void kernel_launch(void* const* d_in, const int* in_sizes, int n_in,
                              void* d_out, int out_size)
{
    (void)in_sizes; (void)n_in; (void)out_size;
    const float* inputs  = (const float*)d_in[0];
    const float* pos_enc = (const float*)d_in[1];
    const float* W_q     = (const float*)d_in[2];
    const float* W_k     = (const float*)d_in[3];
    const float* W_v     = (const float*)d_in[4];
    const float* W_o     = (const float*)d_in[5];
    const float* W_pos   = (const float*)d_in[6];
    const float* u_b     = (const float*)d_in[7];
    const float* v_b     = (const float*)d_in[8];
    float* out = (float*)d_out;

    float *qp, *kp, *vp, *pp, *ap, *cp;
    cudaGetSymbolAddress((void**)&qp, g_Q);
    cudaGetSymbolAddress((void**)&kp, g_K);
    cudaGetSymbolAddress((void**)&vp, g_V);
    cudaGetSymbolAddress((void**)&pp, g_P);
    cudaGetSymbolAddress((void**)&ap, g_A);
    cudaGetSymbolAddress((void**)&cp, g_ctx);

    const int POSA_SMEM  = (2*64*65 + 64*130) * (int)sizeof(float);            // 66560
    const int FLASH_SMEM = (2*64*65 + 64*130 + 128*64) * (int)sizeof(float);   // 99328
    cudaFuncSetAttribute(posA_kernel,
                         cudaFuncAttributeMaxDynamicSharedMemorySize, POSA_SMEM);
    cudaFuncSetAttribute(flash_kernel,
                         cudaFuncAttributeMaxDynamicSharedMemorySize, FLASH_SMEM);
    // max smem carveout so blocks-per-SM is smem-limited at 3/3/2, not carveout
    cudaFuncSetAttribute(posA_kernel,
                         cudaFuncAttributePreferredSharedMemoryCarveout, 100);
    cudaFuncSetAttribute(flash_kernel,
                         cudaFuncAttributePreferredSharedMemoryCarveout, 100);
    cudaFuncSetAttribute(gemm512_kernel<0>,
                         cudaFuncAttributePreferredSharedMemoryCarveout, 100);
    cudaFuncSetAttribute(gemm512_kernel<1>,
                         cudaFuncAttributePreferredSharedMemoryCarveout, 100);

    const dim3 thr(256);
    // projections (head-split layout)
    gemm512_kernel<1><<<dim3(128, 4), thr>>>(inputs,  W_q,   qp);
    gemm512_kernel<1><<<dim3(128, 4), thr>>>(inputs,  W_k,   kp);
    gemm512_kernel<1><<<dim3(128, 4), thr>>>(inputs,  W_v,   vp);
    gemm512_kernel<1><<<dim3(32,  4), thr>>>(pos_enc, W_pos, pp);
    // pos matrix A = (Q+v) @ P^T per (b,h)
    posA_kernel<<<dim3(16, 32, 32), thr, POSA_SMEM>>>(qp, pp, v_b, ap);
    // fused attention -> g_ctx
    flash_kernel<<<dim3(32, 8, 4), thr, FLASH_SMEM>>>(qp, kp, vp, ap, u_b, cp);
    // output projection: ctx @ W_o -> out
    gemm512_kernel<0><<<dim3(128, 4), thr>>>(cp, W_o, out);
}